// round 3
// baseline (speedup 1.0000x reference)
#include <cuda_runtime.h>
#include <cstdint>

// ---------------------------------------------------------------------------
// AdaptiveInput embedding:
//   bucket 0: ids [0,20000)      -> E0 row (d=1024), identity
//   bucket 1: ids [20000,40000)  -> E1 row (d=512)  @ W1^T (1024x512)
//   bucket 2: ids [40000,200000) -> E2 row (d=256)  @ W2^T (1024x256)
//   bucket 3: ids [200000,250000)-> E3 row (d=128)  @ W3^T (1024x128)
// Each token belongs to exactly one bucket -> out row written exactly once.
//
// Robustness measures (no profile available yet; R1 died with IMA, R0/R2 were
// infra failures):
//   (a) inputs bound by unique element count, not position
//   (b) ids dtype auto-detected (int32 vs int64) by a 1-thread prologue
//   (c) static shared memory only (<=48KB), no cudaFuncSetAttribute in capture
//   (d) local row indices clamped per bucket (mirrors reference clip)
// ---------------------------------------------------------------------------

#define NTOK    32
#define THREADS 256
#define DMODEL  1024
#define SMEM_E_FLOATS 8192   // 32 KB staging buffer

// Transposed weights: Wt[k][m] = W[m][k] so GEMV reads W coalesced along m.
__device__ float g_Wt1[512 * 1024];
__device__ float g_Wt2[256 * 1024];
__device__ float g_Wt3[128 * 1024];
__device__ int   g_ids_is64;

__global__ void detect_ids_dtype(const int* __restrict__ ids32, int n32pairs) {
    // int64 ids < 2^31, little-endian: odd int32 positions are all zero.
    // int32 ids: odd positions are uniform in [0, 250000) -> ~never all zero.
    int is64 = 1;
    for (int i = 0; i < n32pairs; i++) {
        if (ids32[2 * i + 1] != 0) { is64 = 0; break; }
    }
    g_ids_is64 = is64;
}

__global__ void transpose_all(const float* __restrict__ W1,
                              const float* __restrict__ W2,
                              const float* __restrict__ W3) {
    int i = blockIdx.x * blockDim.x + threadIdx.x;
    if (i < 1024 * 512) {
        int m = i >> 9, k = i & 511;
        g_Wt1[k * 1024 + m] = W1[i];
    }
    if (i < 1024 * 256) {
        int m = i >> 8, k = i & 255;
        g_Wt2[k * 1024 + m] = W2[i];
    }
    if (i < 1024 * 128) {
        int m = i >> 7, k = i & 127;
        g_Wt3[k * 1024 + m] = W3[i];
    }
}

__device__ __forceinline__ void fma4(float4& a, const float4& w, float s) {
    a.x += w.x * s;
    a.y += w.y * s;
    a.z += w.z * s;
    a.w += w.w * s;
}

// Projected bucket: out[t][m] = sum_k e[t][k] * Wt[k][m]
// Processes the bucket's tokens in chunks of TCHUNK (so the smem tile fits
// 32 KB). Within a chunk: each warp owns 4 tokens, each lane 4 consecutive m
// per 128-wide m-chunk (8 chunks -> 1024).
template <int D, int TCHUNK>
__device__ __forceinline__ void proj_bucket(
    const float* __restrict__ table, const float* __restrict__ Wt, int n,
    const int* __restrict__ list_b, const int* __restrict__ rowbuf,
    float* __restrict__ s_e, float* __restrict__ out, int gbase) {
    const int tid = threadIdx.x;
    const int lane = tid & 31;
    const int wgrp = tid >> 5;   // 0..7

    for (int c0 = 0; c0 < n; c0 += TCHUNK) {
        const int nc = (n - c0) < TCHUNK ? (n - c0) : TCHUNK;

        // stage embedding rows into smem (coalesced within each row)
        for (int idx = tid; idx < nc * D; idx += THREADS) {
            const int t = idx / D;
            const int k = idx - t * D;
            const int row = rowbuf[list_b[c0 + t]];
            s_e[t * D + k] = table[(size_t)row * D + k];
        }
        __syncthreads();

        const int t0 = wgrp * 4;
        if (t0 < nc) {
            const float* e0p = s_e + (t0 + 0) * D;
            const float* e1p = s_e + (t0 + 1 < TCHUNK ? t0 + 1 : t0) * D;
            const float* e2p = s_e + (t0 + 2 < TCHUNK ? t0 + 2 : t0) * D;
            const float* e3p = s_e + (t0 + 3 < TCHUNK ? t0 + 3 : t0) * D;
            const bool v1 = (t0 + 1) < nc;
            const bool v2 = (t0 + 2) < nc;
            const bool v3 = (t0 + 3) < nc;
            const int g0 = gbase + list_b[c0 + t0];
            const int g1 = v1 ? gbase + list_b[c0 + t0 + 1] : 0;
            const int g2 = v2 ? gbase + list_b[c0 + t0 + 2] : 0;
            const int g3 = v3 ? gbase + list_b[c0 + t0 + 3] : 0;

#pragma unroll
            for (int mc = 0; mc < 8; mc++) {
                const int moff = mc * 128 + (lane << 2);
                const float* wp = Wt + moff;
                float4 a0 = make_float4(0.f, 0.f, 0.f, 0.f);
                float4 a1 = a0, a2 = a0, a3 = a0;

#pragma unroll 2
                for (int k = 0; k < D; k += 4) {
                    const float4 w0 = *(const float4*)(wp + (size_t)(k + 0) * DMODEL);
                    const float4 w1 = *(const float4*)(wp + (size_t)(k + 1) * DMODEL);
                    const float4 w2 = *(const float4*)(wp + (size_t)(k + 2) * DMODEL);
                    const float4 w3 = *(const float4*)(wp + (size_t)(k + 3) * DMODEL);
                    const float4 e0 = *(const float4*)(e0p + k);
                    const float4 e1 = *(const float4*)(e1p + k);
                    const float4 e2 = *(const float4*)(e2p + k);
                    const float4 e3 = *(const float4*)(e3p + k);
                    fma4(a0, w0, e0.x); fma4(a0, w1, e0.y);
                    fma4(a0, w2, e0.z); fma4(a0, w3, e0.w);
                    fma4(a1, w0, e1.x); fma4(a1, w1, e1.y);
                    fma4(a1, w2, e1.z); fma4(a1, w3, e1.w);
                    fma4(a2, w0, e2.x); fma4(a2, w1, e2.y);
                    fma4(a2, w2, e2.z); fma4(a2, w3, e2.w);
                    fma4(a3, w0, e3.x); fma4(a3, w1, e3.y);
                    fma4(a3, w2, e3.z); fma4(a3, w3, e3.w);
                }

                *(float4*)(out + (size_t)g0 * DMODEL + moff) = a0;
                if (v1) *(float4*)(out + (size_t)g1 * DMODEL + moff) = a1;
                if (v2) *(float4*)(out + (size_t)g2 * DMODEL + moff) = a2;
                if (v3) *(float4*)(out + (size_t)g3 * DMODEL + moff) = a3;
            }
        }
        __syncthreads();  // s_e reused by next chunk / bucket
    }
}

__global__ __launch_bounds__(THREADS)
void adaptive_input_kernel(const void* __restrict__ ids_raw, int n_tokens,
                           const float* __restrict__ E0,
                           const float* __restrict__ E1,
                           const float* __restrict__ E2,
                           const float* __restrict__ E3,
                           float* __restrict__ out) {
    __shared__ __align__(16) float s_e[SMEM_E_FLOATS];
    __shared__ int cnt[4];
    __shared__ int lists[4][NTOK];
    __shared__ int rowbuf[NTOK];

    const int tid = threadIdx.x;
    const int gbase = blockIdx.x * NTOK;

    if (tid < 4) cnt[tid] = 0;
    __syncthreads();

    if (tid < NTOK && gbase + tid < n_tokens) {
        long long id;
        if (g_ids_is64) {
            id = ((const long long*)ids_raw)[gbase + tid];
        } else {
            id = (long long)((const int*)ids_raw)[gbase + tid];
        }
        int b, lo, rows;
        if (id < 20000)       { b = 0; lo = 0;      rows = 20000; }
        else if (id < 40000)  { b = 1; lo = 20000;  rows = 20000; }
        else if (id < 200000) { b = 2; lo = 40000;  rows = 160000; }
        else                  { b = 3; lo = 200000; rows = 50000; }
        int local = (int)(id - lo);
        local = local < 0 ? 0 : (local >= rows ? rows - 1 : local);
        rowbuf[tid] = local;
        const int p = atomicAdd(&cnt[b], 1);
        lists[b][p] = tid;
    }
    __syncthreads();

    // bucket 0: straight row copy (1024 floats = 256 x float4)
    {
        const int n0 = cnt[0];
        for (int i = 0; i < n0; i++) {
            const int lt = lists[0][i];
            const int row = rowbuf[lt];
            const float4* src = (const float4*)(E0 + (size_t)row * DMODEL);
            float4* dst = (float4*)(out + (size_t)(gbase + lt) * DMODEL);
            dst[tid] = src[tid];
        }
    }

    proj_bucket<512, 16>(E1, g_Wt1, cnt[1], lists[1], rowbuf, s_e, out, gbase);
    proj_bucket<256, 32>(E2, g_Wt2, cnt[2], lists[2], rowbuf, s_e, out, gbase);
    proj_bucket<128, 32>(E3, g_Wt3, cnt[3], lists[3], rowbuf, s_e, out, gbase);
}

extern "C" void kernel_launch(void* const* d_in, const int* in_sizes, int n_in,
                              void* d_out, int out_size) {
    // Bind inputs by element count — every input has a unique size:
    //   input_ids 8*4096 = 32768
    //   E0 20000*1024 = 20480000    E1 20000*512 = 10240000
    //   E2 160000*256 = 40960000    E3 50000*128 = 6400000
    //   W1 1024*512 = 524288  W2 1024*256 = 262144  W3 1024*128 = 131072
    const void* ids = nullptr;
    const float *E0 = nullptr, *E1 = nullptr, *E2 = nullptr, *E3 = nullptr;
    const float *W1 = nullptr, *W2 = nullptr, *W3 = nullptr;
    int n_tokens = 0;

    for (int i = 0; i < n_in; i++) {
        switch (in_sizes[i]) {
            case 32768:    ids = d_in[i]; n_tokens = in_sizes[i]; break;
            case 20480000: E0 = (const float*)d_in[i]; break;
            case 10240000: E1 = (const float*)d_in[i]; break;
            case 40960000: E2 = (const float*)d_in[i]; break;
            case 6400000:  E3 = (const float*)d_in[i]; break;
            case 524288:   W1 = (const float*)d_in[i]; break;
            case 262144:   W2 = (const float*)d_in[i]; break;
            case 131072:   W3 = (const float*)d_in[i]; break;
            default: break;
        }
    }
    if (!ids || !E0 || !E1 || !E2 || !E3 || !W1 || !W2 || !W3) {
        ids = d_in[0]; n_tokens = in_sizes[0];
        E0 = (const float*)d_in[1]; E1 = (const float*)d_in[2];
        E2 = (const float*)d_in[3]; E3 = (const float*)d_in[4];
        W1 = (const float*)d_in[5]; W2 = (const float*)d_in[6];
        W3 = (const float*)d_in[7];
    }

    float* out = (float*)d_out;

    detect_ids_dtype<<<1, 1>>>((const int*)ids, 512);
    transpose_all<<<(1024 * 512 + 255) / 256, 256>>>(W1, W2, W3);

    const int grid = (n_tokens + NTOK - 1) / NTOK;
    adaptive_input_kernel<<<grid, THREADS>>>(ids, n_tokens, E0, E1, E2, E3, out);
}

// round 4
// speedup vs baseline: 2.4233x; 2.4233x over previous
#include <cuda_runtime.h>
#include <cstdint>

// ---------------------------------------------------------------------------
// AdaptiveInput embedding, R4: global compaction + dense per-bucket GEMV.
//   bucket 0: ids [0,20000)      -> E0 row (d=1024), identity copy
//   bucket 1: ids [20000,40000)  -> E1 row (d=512)  @ W1^T
//   bucket 2: ids [40000,200000) -> E2 row (d=256)  @ W2^T
//   bucket 3: ids [200000,250000)-> E3 row (d=128)  @ W3^T
//
// Pipeline per replay (all in one graph):
//   1. detect_reset: ids dtype sniff + zero bucket counters
//   2. transpose_all: W[m][k] -> Wt[k][m] device globals
//   3. classify: compact (token, local_row) into per-bucket lists
//   4. copy_b0: dense bucket-0 row copies
//   5. gemm: each CTA owns one dense tile of same-bucket tokens
// ---------------------------------------------------------------------------

#define THREADS 256
#define DMODEL  1024
#define MAXTOK  32768

__device__ float g_Wt1[512 * 1024];
__device__ float g_Wt2[256 * 1024];
__device__ float g_Wt3[128 * 1024];
__device__ int   g_ids_is64;
__device__ int   g_cnt[4];
__device__ int   g_tok[4][MAXTOK];
__device__ int   g_row[4][MAXTOK];

__global__ void detect_reset(const int* __restrict__ ids32, int npairs) {
    // int64 ids < 2^31 little-endian: odd int32 words all zero.
    int is64 = 1;
    for (int i = 0; i < npairs; i++)
        if (ids32[2 * i + 1] != 0) { is64 = 0; break; }
    g_ids_is64 = is64;
    g_cnt[0] = 0; g_cnt[1] = 0; g_cnt[2] = 0; g_cnt[3] = 0;
}

__global__ void transpose_all(const float* __restrict__ W1,
                              const float* __restrict__ W2,
                              const float* __restrict__ W3) {
    int i = blockIdx.x * blockDim.x + threadIdx.x;
    if (i < 1024 * 512) {
        int m = i >> 9, k = i & 511;
        g_Wt1[k * 1024 + m] = W1[i];
    }
    if (i < 1024 * 256) {
        int m = i >> 8, k = i & 255;
        g_Wt2[k * 1024 + m] = W2[i];
    }
    if (i < 1024 * 128) {
        int m = i >> 7, k = i & 127;
        g_Wt3[k * 1024 + m] = W3[i];
    }
}

__global__ void classify(const void* __restrict__ ids_raw, int n_tokens) {
    int i = blockIdx.x * blockDim.x + threadIdx.x;
    if (i >= n_tokens) return;
    long long id = g_ids_is64 ? ((const long long*)ids_raw)[i]
                              : (long long)((const int*)ids_raw)[i];
    int b, lo, rows;
    if (id < 20000)       { b = 0; lo = 0;      rows = 20000; }
    else if (id < 40000)  { b = 1; lo = 20000;  rows = 20000; }
    else if (id < 200000) { b = 2; lo = 40000;  rows = 160000; }
    else                  { b = 3; lo = 200000; rows = 50000; }
    int local = (int)(id - lo);
    local = local < 0 ? 0 : (local >= rows ? rows - 1 : local);
    int pos = atomicAdd(&g_cnt[b], 1);
    g_tok[b][pos] = i;
    g_row[b][pos] = local;
}

// 8 rows per CTA; 256 threads x float4 = one full 1024-float row per pass.
__global__ __launch_bounds__(THREADS)
void copy_b0(const float* __restrict__ E0, float* __restrict__ out) {
    const int c0 = g_cnt[0];
    const int r0 = blockIdx.x * 8;
    if (r0 >= c0) return;
    const int tid = threadIdx.x;
#pragma unroll
    for (int j = 0; j < 8; j++) {
        const int r = r0 + j;
        if (r < c0) {
            const int row = g_row[0][r];
            const int tok = g_tok[0][r];
            const float4* src = (const float4*)(E0 + (size_t)row * DMODEL);
            float4* dst = (float4*)(out + (size_t)tok * DMODEL);
            dst[tid] = src[tid];
        }
    }
}

__device__ __forceinline__ void fma4(float4& a, const float4& w, float s) {
    a.x += w.x * s;
    a.y += w.y * s;
    a.z += w.z * s;
    a.w += w.w * s;
}

// Dense same-bucket tile: TPC = 8*TPW tokens. Each warp owns TPW tokens;
// each lane owns 4 consecutive m per 128-wide m-chunk (8 chunks -> 1024).
template <int D, int TPW>
__device__ __forceinline__ void proj_tile(
    const float* __restrict__ table, const float* __restrict__ Wt,
    const int* __restrict__ toklist, const int* __restrict__ rowlist,
    int cnt, int tile, float* __restrict__ s_e, float* __restrict__ out) {
    constexpr int TPC = 8 * TPW;
    const int tid = threadIdx.x;
    const int lane = tid & 31;
    const int wgrp = tid >> 5;
    const int t0 = tile * TPC;
    const int n = (cnt - t0) < TPC ? (cnt - t0) : TPC;

    // stage embedding rows (coalesced within each row)
    for (int idx = tid; idx < n * D; idx += THREADS) {
        const int t = idx / D;             // D is power of two -> shift
        const int k = idx - t * D;
        s_e[t * D + k] = table[(size_t)rowlist[t0 + t] * D + k];
    }
    __syncthreads();

    const int tb = wgrp * TPW;
    bool valid[TPW];
    int gout[TPW];
    const float* eptr[TPW];
#pragma unroll
    for (int j = 0; j < TPW; j++) {
        valid[j] = (tb + j) < n;
        gout[j] = valid[j] ? toklist[t0 + tb + j] : 0;
        eptr[j] = s_e + (valid[j] ? (tb + j) : 0) * D;
    }

    if (tb < n) {
#pragma unroll
        for (int mc = 0; mc < 8; mc++) {
            const int moff = mc * 128 + (lane << 2);
            const float* wp = Wt + moff;
            float4 acc[TPW];
#pragma unroll
            for (int j = 0; j < TPW; j++)
                acc[j] = make_float4(0.f, 0.f, 0.f, 0.f);

#pragma unroll 4
            for (int k = 0; k < D; k += 4) {
                const float4 w0 = *(const float4*)(wp + (size_t)(k + 0) * DMODEL);
                const float4 w1 = *(const float4*)(wp + (size_t)(k + 1) * DMODEL);
                const float4 w2 = *(const float4*)(wp + (size_t)(k + 2) * DMODEL);
                const float4 w3 = *(const float4*)(wp + (size_t)(k + 3) * DMODEL);
#pragma unroll
                for (int j = 0; j < TPW; j++) {
                    const float4 e = *(const float4*)(eptr[j] + k);
                    fma4(acc[j], w0, e.x);
                    fma4(acc[j], w1, e.y);
                    fma4(acc[j], w2, e.z);
                    fma4(acc[j], w3, e.w);
                }
            }

#pragma unroll
            for (int j = 0; j < TPW; j++)
                if (valid[j])
                    *(float4*)(out + (size_t)gout[j] * DMODEL + moff) = acc[j];
        }
    }
}

// Grid covers worst case; CTA maps itself to (bucket, tile) from counters.
__global__ __launch_bounds__(THREADS)
void gemm_kernel(const float* __restrict__ E1,
                 const float* __restrict__ E2,
                 const float* __restrict__ E3,
                 float* __restrict__ out) {
    __shared__ __align__(16) float s_e[8192];  // 32 KB

    const int c1 = g_cnt[1], c2 = g_cnt[2], c3 = g_cnt[3];
    const int nb1 = (c1 + 15) >> 4;   // 16 tokens/CTA for d=512
    const int nb2 = (c2 + 31) >> 5;   // 32 tokens/CTA for d=256
    const int nb3 = (c3 + 31) >> 5;   // 32 tokens/CTA for d=128
    const int b = blockIdx.x;

    if (b < nb1) {
        proj_tile<512, 2>(E1, g_Wt1, g_tok[1], g_row[1], c1, b, s_e, out);
    } else if (b < nb1 + nb2) {
        proj_tile<256, 4>(E2, g_Wt2, g_tok[2], g_row[2], c2, b - nb1, s_e, out);
    } else if (b < nb1 + nb2 + nb3) {
        proj_tile<128, 4>(E3, g_Wt3, g_tok[3], g_row[3], c3, b - nb1 - nb2, s_e, out);
    }
}

extern "C" void kernel_launch(void* const* d_in, const int* in_sizes, int n_in,
                              void* d_out, int out_size) {
    // Bind inputs by unique element count (ordering-proof):
    //   input_ids 32768; E0 20480000; E1 10240000; E2 40960000; E3 6400000;
    //   W1 524288; W2 262144; W3 131072
    const void* ids = nullptr;
    const float *E0 = nullptr, *E1 = nullptr, *E2 = nullptr, *E3 = nullptr;
    const float *W1 = nullptr, *W2 = nullptr, *W3 = nullptr;
    int n_tokens = 0;

    for (int i = 0; i < n_in; i++) {
        switch (in_sizes[i]) {
            case 32768:    ids = d_in[i]; n_tokens = in_sizes[i]; break;
            case 20480000: E0 = (const float*)d_in[i]; break;
            case 10240000: E1 = (const float*)d_in[i]; break;
            case 40960000: E2 = (const float*)d_in[i]; break;
            case 6400000:  E3 = (const float*)d_in[i]; break;
            case 524288:   W1 = (const float*)d_in[i]; break;
            case 262144:   W2 = (const float*)d_in[i]; break;
            case 131072:   W3 = (const float*)d_in[i]; break;
            default: break;
        }
    }
    if (!ids || !E0 || !E1 || !E2 || !E3 || !W1 || !W2 || !W3) {
        ids = d_in[0]; n_tokens = in_sizes[0];
        E0 = (const float*)d_in[1]; E1 = (const float*)d_in[2];
        E2 = (const float*)d_in[3]; E3 = (const float*)d_in[4];
        W1 = (const float*)d_in[5]; W2 = (const float*)d_in[6];
        W3 = (const float*)d_in[7];
    }

    float* out = (float*)d_out;

    detect_reset<<<1, 1>>>((const int*)ids, 64);
    transpose_all<<<(1024 * 512 + 255) / 256, 256>>>(W1, W2, W3);
    classify<<<(n_tokens + THREADS - 1) / THREADS, THREADS>>>(ids, n_tokens);
    copy_b0<<<(n_tokens + 7) / 8, THREADS>>>(E0, out);

    // Worst case: all tokens in bucket 1 -> 32768/16 = 2048 tiles (+ceil slack)
    gemm_kernel<<<2052, THREADS>>>(E1, E2, E3, out);
}